// round 2
// baseline (speedup 1.0000x reference)
#include <cuda_runtime.h>
#include <math.h>

// ---------------------------------------------------------------------------
// LFQ forward, B=4, DIM=512, T=2048, codebook_dim=14, NB_CODE=16384
// d_out layout (float32): out[4*512*2048] | indices[4*2048] | aux_loss[1]
// ---------------------------------------------------------------------------

#define DIM_ 512
#define T_   2048
#define N_   8192          // B*T samples
#define C_   14
#define J_   16384
#define DCH  128           // d-chunk for in/out projection kernels
#define NCH  4             // 512 / 128
#define OUT_IDX  4194304   // 4*512*2048
#define OUT_LOSS 4202496   // OUT_IDX + 8192

#define BBLK   128         // blocks for avg-prob kernel
#define BNS    64          // samples per avg block  (128*64 = 8192)
#define BBATCH 8           // samples per shared-mem batch

// Static scratch (no allocations allowed)
__device__ float g_hpart[NCH * C_ * N_];   // partial h, layout [chunk][c][n]
__device__ float g_p[N_ * 16];             // p(bit c = 1), padded to 16/sample
__device__ int   g_idx[N_];
__device__ float g_Ap[64];                 // 32 blocks x {commit, entropy}
__device__ float g_Bp[BBLK * J_];          // partial avg_prob sums
__device__ float g_Cp[64];                 // codebook-entropy partials

// ---------------------------------------------------------------------------
// Kernel 1: partial in-projection.  h_part[chunk,c,n] = sum_{d in chunk} x*Win
// grid = 32 n-tiles * 4 d-chunks = 128 blocks, 256 threads (1 sample each)
// ---------------------------------------------------------------------------
__global__ void __launch_bounds__(256) k_inproj(const float* __restrict__ x,
                                                const float* __restrict__ Win) {
    __shared__ float ws[DCH][16];
    int chunk = blockIdx.x & 3;
    int ntile = blockIdx.x >> 2;
    int d0 = chunk * DCH;
    for (int i = threadIdx.x; i < DCH * 16; i += 256) {
        int dd = i >> 4, c = i & 15;
        ws[dd][c] = (c < C_) ? Win[c * DIM_ + d0 + dd] : 0.f;
    }
    __syncthreads();

    int n = ntile * 256 + threadIdx.x;
    int b = n >> 11, t = n & 2047;
    const float* xp = x + ((size_t)(b * DIM_ + d0)) * T_ + t;

    float acc[C_];
#pragma unroll
    for (int c = 0; c < C_; c++) acc[c] = 0.f;

#pragma unroll 4
    for (int dd = 0; dd < DCH; dd++) {
        float xv = xp[(size_t)dd * T_];                    // coalesced over t
        const float4* w4 = reinterpret_cast<const float4*>(ws[dd]);  // broadcast
        float4 w0 = w4[0], w1 = w4[1], w2 = w4[2], w3 = w4[3];
        acc[0]  += xv * w0.x; acc[1]  += xv * w0.y; acc[2]  += xv * w0.z; acc[3]  += xv * w0.w;
        acc[4]  += xv * w1.x; acc[5]  += xv * w1.y; acc[6]  += xv * w1.z; acc[7]  += xv * w1.w;
        acc[8]  += xv * w2.x; acc[9]  += xv * w2.y; acc[10] += xv * w2.z; acc[11] += xv * w2.w;
        acc[12] += xv * w3.x; acc[13] += xv * w3.y;
    }
#pragma unroll
    for (int c = 0; c < C_; c++)
        g_hpart[(chunk * C_ + c) * N_ + n] = acc[c];       // coalesced over n
}

// ---------------------------------------------------------------------------
// Kernel 2: assemble h, compute index / commit / per-sample entropy / p.
// grid = 32 blocks x 256 threads (1 sample each)
// ---------------------------------------------------------------------------
__global__ void __launch_bounds__(256) k_mid(const float* __restrict__ bin,
                                             float* __restrict__ dout) {
    int n = blockIdx.x * 256 + threadIdx.x;

    float h[C_];
#pragma unroll
    for (int c = 0; c < C_; c++) {
        float v = bin[c];
#pragma unroll
        for (int ch = 0; ch < NCH; ch++) v += g_hpart[(ch * C_ + c) * N_ + n];
        h[c] = v;
    }

    int idx = 0;
    float commit = 0.f, ent = 0.f;
#pragma unroll
    for (int c = 0; c < C_; c++) {
        float hv = h[c];
        bool pos = hv > 0.f;
        float q = pos ? 1.f : -1.f;
        if (pos) idx |= (1 << (13 - c));
        float d = hv - q;
        commit += d * d;
        // p(bit set) = sigmoid(400 h).  z = exp(-400|h|) keeps full relative
        // precision on the small side (matches max-subtracted softmax).
        float z   = __expf(-400.f * fabsf(hv));
        float pb  = 1.f / (1.f + z);   // big side
        float psm = z * pb;            // small side
        float e = -pb * __logf(pb);
        if (psm > 0.f) e -= psm * __logf(psm);
        ent += e;
        g_p[n * 16 + c] = pos ? pb : psm;
    }
    g_p[n * 16 + 14] = 0.f;
    g_p[n * 16 + 15] = 0.f;
    g_idx[n] = idx;
    dout[OUT_IDX + n] = (float)idx;

    // deterministic block reduction of (commit, entropy)
    __shared__ float sr[512];
    sr[threadIdx.x] = commit;
    sr[256 + threadIdx.x] = ent;
    __syncthreads();
    for (int s = 128; s > 0; s >>= 1) {
        if (threadIdx.x < s) {
            sr[threadIdx.x]       += sr[threadIdx.x + s];
            sr[256 + threadIdx.x] += sr[256 + threadIdx.x + s];
        }
        __syncthreads();
    }
    if (threadIdx.x == 0) {
        g_Ap[blockIdx.x * 2]     = sr[0];
        g_Ap[blockIdx.x * 2 + 1] = sr[256];
    }
}

// ---------------------------------------------------------------------------
// Kernel 3: out-projection  out[b,d,t] = sum_c Wout[d,c]*s_c + bout[d]
// grid = 32 n-tiles * 4 d-chunks = 128 blocks, 256 threads (1 sample each)
// ---------------------------------------------------------------------------
__global__ void __launch_bounds__(256) k_outproj(const float* __restrict__ Wout,
                                                 const float* __restrict__ bout,
                                                 float* __restrict__ out) {
    __shared__ float ws[DCH][16];
    __shared__ float bo[DCH];
    int chunk = blockIdx.x & 3;
    int ntile = blockIdx.x >> 2;
    int d0 = chunk * DCH;
    for (int i = threadIdx.x; i < DCH * 16; i += 256) {
        int dd = i >> 4, c = i & 15;
        ws[dd][c] = (c < C_) ? Wout[(d0 + dd) * C_ + c] : 0.f;
    }
    for (int i = threadIdx.x; i < DCH; i += 256) bo[i] = bout[d0 + i];
    __syncthreads();

    int n = ntile * 256 + threadIdx.x;
    int b = n >> 11, t = n & 2047;
    int idx = g_idx[n];
    float s[C_];
#pragma unroll
    for (int c = 0; c < C_; c++) s[c] = ((idx >> (13 - c)) & 1) ? 1.f : -1.f;

    float* op = out + ((size_t)(b * DIM_ + d0)) * T_ + t;
#pragma unroll 2
    for (int dd = 0; dd < DCH; dd++) {
        const float4* w4 = reinterpret_cast<const float4*>(ws[dd]);
        float4 w0 = w4[0], w1 = w4[1], w2 = w4[2], w3 = w4[3];
        float r = bo[dd];
        r += w0.x * s[0]  + w0.y * s[1]  + w0.z * s[2]  + w0.w * s[3];
        r += w1.x * s[4]  + w1.y * s[5]  + w1.z * s[6]  + w1.w * s[7];
        r += w2.x * s[8]  + w2.y * s[9]  + w2.z * s[10] + w2.w * s[11];
        r += w3.x * s[12] + w3.y * s[13];
        op[(size_t)dd * T_] = r;                           // coalesced over t
    }
}

// ---------------------------------------------------------------------------
// Kernel 4: avg_prob partial sums.
// prob_n[j] = Hi_n[j>>7] * Lo_n[j&127]  (7-bit half products from p).
// Each thread owns 32 j-slots in registers; block handles 64 samples.
// grid = 128 blocks x 512 threads
// ---------------------------------------------------------------------------
__global__ void __launch_bounds__(512) k_avg() {
    __shared__ float pss[BBATCH][16];
    __shared__ float LoS[BBATCH][128];
    __shared__ float HiS[BBATCH][128];
    int t = threadIdx.x;

    float acc[32];
#pragma unroll
    for (int i = 0; i < 32; i++) acc[i] = 0.f;

    int jh  = t >> 2;            // constant per thread: j = jh*128 + lo0 + i
    int lo0 = (t & 3) * 32;

    int n0 = blockIdx.x * BNS;
    for (int bat = 0; bat < BNS / BBATCH; bat++) {
        int nb = n0 + bat * BBATCH;
        __syncthreads();   // protect Lo/Hi/pss reuse from previous batch
        if (t < BBATCH * 16)
            pss[t >> 4][t & 15] = g_p[(nb + (t >> 4)) * 16 + (t & 15)];
        __syncthreads();

        // 2048 half-product jobs over 512 threads
#pragma unroll
        for (int rep = 0; rep < (BBATCH * 256) / 512; rep++) {
            int job  = t + rep * 512;
            int s    = job >> 8;
            int role = (job >> 7) & 1;   // 0 = Lo (bits c=13..7), 1 = Hi (c=6..0)
            int jl   = job & 127;
            float v = 1.f;
#pragma unroll
            for (int k = 0; k < 7; k++) {
                float pc = pss[s][role ? (6 - k) : (13 - k)];
                v *= ((jl >> k) & 1) ? pc : (1.f - pc);
            }
            if (role) HiS[s][jl] = v; else LoS[s][jl] = v;
        }
        __syncthreads();

#pragma unroll
        for (int s = 0; s < BBATCH; s++) {
            float hv = HiS[s][jh];
            const float4* lp = reinterpret_cast<const float4*>(&LoS[s][lo0]);
#pragma unroll
            for (int i = 0; i < 8; i++) {
                float4 l = lp[i];
                acc[i * 4 + 0] += hv * l.x;
                acc[i * 4 + 1] += hv * l.y;
                acc[i * 4 + 2] += hv * l.z;
                acc[i * 4 + 3] += hv * l.w;
            }
        }
    }
    // coalesced dump; element (i*512 + t) of this block's partial is code
    // jh*128+lo0+i, identical mapping in every block, and downstream sums are
    // order-independent so no remap is needed.
#pragma unroll
    for (int i = 0; i < 32; i++)
        g_Bp[blockIdx.x * J_ + i * 512 + t] = acc[i];
}

// ---------------------------------------------------------------------------
// Kernel 5: reduce partials over blocks -> avg_prob -> entropy terms.
// grid = 64 blocks x 256 threads (one code slot each)
// ---------------------------------------------------------------------------
__global__ void __launch_bounds__(256) k_cred() {
    int e = blockIdx.x * 256 + threadIdx.x;
    float sum = 0.f;
#pragma unroll 8
    for (int blk = 0; blk < BBLK; blk++) sum += g_Bp[blk * J_ + e];
    float avg  = sum * (1.f / 8192.f);
    float entc = -avg * __logf(fmaxf(avg, 1e-20f));

    __shared__ float sr[256];
    sr[threadIdx.x] = entc;
    __syncthreads();
    for (int s = 128; s > 0; s >>= 1) {
        if (threadIdx.x < s) sr[threadIdx.x] += sr[threadIdx.x + s];
        __syncthreads();
    }
    if (threadIdx.x == 0) g_Cp[blockIdx.x] = sr[0];
}

// ---------------------------------------------------------------------------
// Kernel 6: final combine -> aux_loss
// ---------------------------------------------------------------------------
__global__ void k_final(float* __restrict__ dout) {
    int t = threadIdx.x;   // 32 threads
    float cb = g_Cp[t] + g_Cp[t + 32];
    float cm = g_Ap[2 * t];
    float en = g_Ap[2 * t + 1];
#pragma unroll
    for (int o = 16; o > 0; o >>= 1) {
        cb += __shfl_down_sync(0xffffffffu, cb, o);
        cm += __shfl_down_sync(0xffffffffu, cm, o);
        en += __shfl_down_sync(0xffffffffu, en, o);
    }
    if (t == 0) {
        float ps_mean     = en / 8192.f;
        float commit_mean = cm / (8192.f * 14.f);
        // aux = 0.1*(per_sample_entropy - 1.0*codebook_entropy) + 1.0*commit
        dout[OUT_LOSS] = 0.1f * (ps_mean - cb) + commit_mean;
    }
}

// ---------------------------------------------------------------------------
extern "C" void kernel_launch(void* const* d_in, const int* in_sizes, int n_in,
                              void* d_out, int out_size) {
    const float* x    = (const float*)d_in[0];
    const float* Win  = (const float*)d_in[1];
    const float* bin  = (const float*)d_in[2];
    const float* Wout = (const float*)d_in[3];
    const float* bout = (const float*)d_in[4];
    float* out = (float*)d_out;

    k_inproj<<<128, 256>>>(x, Win);
    k_mid<<<32, 256>>>(bin, out);
    k_outproj<<<128, 256>>>(Wout, bout, out);
    k_avg<<<BBLK, 512>>>();
    k_cred<<<64, 256>>>();
    k_final<<<1, 32>>>(out);
}

// round 3
// speedup vs baseline: 2.1765x; 2.1765x over previous
#include <cuda_runtime.h>
#include <math.h>

// ---------------------------------------------------------------------------
// LFQ forward, B=4, DIM=512, T=2048, codebook_dim=14, NB_CODE=16384
// d_out layout (float32): out[4*512*2048] | indices[4*2048] | aux_loss[1]
// ---------------------------------------------------------------------------

#define DIM_ 512
#define T_   2048
#define N_   8192          // B*T samples
#define C_   14
#define J_   16384
#define DCH  128           // d-chunk for in/out projection kernels
#define NCH  4             // 512 / 128
#define OUT_IDX  4194304   // 4*512*2048
#define OUT_LOSS 4202496   // OUT_IDX + 8192

#define BBLK   128         // blocks for avg-prob kernel
#define BNS    64          // samples per avg block  (128*64 = 8192)
#define BBATCH 16          // samples per shared-mem batch

// Static scratch (no allocations allowed)
__device__ float g_hpart[NCH * C_ * N_];   // partial h, layout [chunk][c][n]
__device__ float g_p[N_ * 16];             // p(bit c = 1), padded to 16/sample
__device__ int   g_idx[N_];
__device__ float g_Ap[64];                 // 32 blocks x {commit, entropy}
__device__ float g_Bp[BBLK * J_];          // partial avg_prob sums
__device__ float g_Cp[64];                 // codebook-entropy partials

// ---------------------------------------------------------------------------
// Kernel 1: partial in-projection.  h_part[chunk,c,n] = sum_{d in chunk} x*Win
// grid = 32 n-tiles * 4 d-chunks = 128 blocks, 256 threads (1 sample each)
// ---------------------------------------------------------------------------
__global__ void __launch_bounds__(256) k_inproj(const float* __restrict__ x,
                                                const float* __restrict__ Win) {
    __shared__ float ws[DCH][16];
    int chunk = blockIdx.x & 3;
    int ntile = blockIdx.x >> 2;
    int d0 = chunk * DCH;
    for (int i = threadIdx.x; i < DCH * 16; i += 256) {
        int dd = i >> 4, c = i & 15;
        ws[dd][c] = (c < C_) ? Win[c * DIM_ + d0 + dd] : 0.f;
    }
    __syncthreads();

    int n = ntile * 256 + threadIdx.x;
    int b = n >> 11, t = n & 2047;
    const float* xp = x + ((size_t)(b * DIM_ + d0)) * T_ + t;

    float acc[C_];
#pragma unroll
    for (int c = 0; c < C_; c++) acc[c] = 0.f;

#pragma unroll 4
    for (int dd = 0; dd < DCH; dd++) {
        float xv = xp[(size_t)dd * T_];                    // coalesced over t
        const float4* w4 = reinterpret_cast<const float4*>(ws[dd]);  // broadcast
        float4 w0 = w4[0], w1 = w4[1], w2 = w4[2], w3 = w4[3];
        acc[0]  += xv * w0.x; acc[1]  += xv * w0.y; acc[2]  += xv * w0.z; acc[3]  += xv * w0.w;
        acc[4]  += xv * w1.x; acc[5]  += xv * w1.y; acc[6]  += xv * w1.z; acc[7]  += xv * w1.w;
        acc[8]  += xv * w2.x; acc[9]  += xv * w2.y; acc[10] += xv * w2.z; acc[11] += xv * w2.w;
        acc[12] += xv * w3.x; acc[13] += xv * w3.y;
    }
#pragma unroll
    for (int c = 0; c < C_; c++)
        g_hpart[(chunk * C_ + c) * N_ + n] = acc[c];       // coalesced over n
}

// ---------------------------------------------------------------------------
// Kernel 2: assemble h, compute index / commit / per-sample entropy / p.
// grid = 32 blocks x 256 threads (1 sample each)
// ---------------------------------------------------------------------------
__global__ void __launch_bounds__(256) k_mid(const float* __restrict__ bin,
                                             float* __restrict__ dout) {
    int n = blockIdx.x * 256 + threadIdx.x;

    float h[C_];
#pragma unroll
    for (int c = 0; c < C_; c++) {
        float v = bin[c];
#pragma unroll
        for (int ch = 0; ch < NCH; ch++) v += g_hpart[(ch * C_ + c) * N_ + n];
        h[c] = v;
    }

    int idx = 0;
    float commit = 0.f, ent = 0.f;
#pragma unroll
    for (int c = 0; c < C_; c++) {
        float hv = h[c];
        bool pos = hv > 0.f;
        float q = pos ? 1.f : -1.f;
        if (pos) idx |= (1 << (13 - c));
        float d = hv - q;
        commit += d * d;
        // p(bit set) = sigmoid(400 h).  z = exp(-400|h|) keeps full relative
        // precision on the small side (matches max-subtracted softmax).
        float z   = __expf(-400.f * fabsf(hv));
        float pb  = 1.f / (1.f + z);   // big side
        float psm = z * pb;            // small side
        float e = -pb * __logf(pb);
        if (psm > 0.f) e -= psm * __logf(psm);
        ent += e;
        g_p[n * 16 + c] = pos ? pb : psm;
    }
    g_p[n * 16 + 14] = 0.f;
    g_p[n * 16 + 15] = 0.f;
    g_idx[n] = idx;
    dout[OUT_IDX + n] = (float)idx;

    // deterministic block reduction of (commit, entropy)
    __shared__ float sr[512];
    sr[threadIdx.x] = commit;
    sr[256 + threadIdx.x] = ent;
    __syncthreads();
    for (int s = 128; s > 0; s >>= 1) {
        if (threadIdx.x < s) {
            sr[threadIdx.x]       += sr[threadIdx.x + s];
            sr[256 + threadIdx.x] += sr[256 + threadIdx.x + s];
        }
        __syncthreads();
    }
    if (threadIdx.x == 0) {
        g_Ap[blockIdx.x * 2]     = sr[0];
        g_Ap[blockIdx.x * 2 + 1] = sr[256];
    }
}

// ---------------------------------------------------------------------------
// Kernel 3: out-projection  out[b,d,t] = sum_c Wout[d,c]*s_c + bout[d]
// grid = 32 n-tiles * 4 d-chunks = 128 blocks, 256 threads (1 sample each)
// ---------------------------------------------------------------------------
__global__ void __launch_bounds__(256) k_outproj(const float* __restrict__ Wout,
                                                 const float* __restrict__ bout,
                                                 float* __restrict__ out) {
    __shared__ float ws[DCH][16];
    __shared__ float bo[DCH];
    int chunk = blockIdx.x & 3;
    int ntile = blockIdx.x >> 2;
    int d0 = chunk * DCH;
    for (int i = threadIdx.x; i < DCH * 16; i += 256) {
        int dd = i >> 4, c = i & 15;
        ws[dd][c] = (c < C_) ? Wout[(d0 + dd) * C_ + c] : 0.f;
    }
    for (int i = threadIdx.x; i < DCH; i += 256) bo[i] = bout[d0 + i];
    __syncthreads();

    int n = ntile * 256 + threadIdx.x;
    int b = n >> 11, t = n & 2047;
    int idx = g_idx[n];
    float s[C_];
#pragma unroll
    for (int c = 0; c < C_; c++) s[c] = ((idx >> (13 - c)) & 1) ? 1.f : -1.f;

    float* op = out + ((size_t)(b * DIM_ + d0)) * T_ + t;
#pragma unroll 2
    for (int dd = 0; dd < DCH; dd++) {
        const float4* w4 = reinterpret_cast<const float4*>(ws[dd]);
        float4 w0 = w4[0], w1 = w4[1], w2 = w4[2], w3 = w4[3];
        float r = bo[dd];
        r += w0.x * s[0]  + w0.y * s[1]  + w0.z * s[2]  + w0.w * s[3];
        r += w1.x * s[4]  + w1.y * s[5]  + w1.z * s[6]  + w1.w * s[7];
        r += w2.x * s[8]  + w2.y * s[9]  + w2.z * s[10] + w2.w * s[11];
        r += w3.x * s[12] + w3.y * s[13];
        op[(size_t)dd * T_] = r;                           // coalesced over t
    }
}

// ---------------------------------------------------------------------------
// Kernel 4: avg_prob partial sums  (register-blocked 128x128xK outer product)
// prob_n[j] = Hi_n[j>>7] * Lo_n[j&127]  (7-bit half products from p).
// Thread tile: 8 jh x 4 jl in registers.  jl0=(t&31)*4 (coalesced/full-cover),
// jh0=(t>>5)*8 (warp-uniform -> broadcast LDS).  6 smem wavefronts + 32 FMA
// per warp per sample -> FMA-bound.
// grid = 128 blocks x 512 threads, 64 samples/block
// ---------------------------------------------------------------------------
__global__ void __launch_bounds__(512) k_avg() {
    __shared__ float pss[BBATCH][16];
    __shared__ float LoS[BBATCH][128];
    __shared__ float HiS[BBATCH][128];
    int t = threadIdx.x;
    int jl0 = (t & 31) * 4;
    int jh0 = (t >> 5) * 8;

    float4 acc[8];
#pragma unroll
    for (int a = 0; a < 8; a++) acc[a] = make_float4(0.f, 0.f, 0.f, 0.f);

    int n0 = blockIdx.x * BNS;
    for (int bat = 0; bat < BNS / BBATCH; bat++) {
        int nb = n0 + bat * BBATCH;
        __syncthreads();   // protect Lo/Hi/pss reuse from previous batch
        if (t < BBATCH * 16)
            pss[t >> 4][t & 15] = g_p[nb * 16 + t];        // contiguous, coalesced
        __syncthreads();

        // half-product production: BBATCH*256 jobs over 512 threads
#pragma unroll
        for (int rep = 0; rep < (BBATCH * 256) / 512; rep++) {
            int job  = t + rep * 512;
            int s    = job >> 8;
            int role = (job >> 7) & 1;   // 0 = Lo (bits c=13..7), 1 = Hi (c=6..0)
            int jl   = job & 127;
            float v = 1.f;
#pragma unroll
            for (int k = 0; k < 7; k++) {
                float pc = pss[s][role ? (6 - k) : (13 - k)];
                v *= ((jl >> k) & 1) ? pc : (1.f - pc);
            }
            if (role) HiS[s][jl] = v; else LoS[s][jl] = v;
        }
        __syncthreads();

#pragma unroll
        for (int s = 0; s < BBATCH; s++) {
            float4 lo  = *reinterpret_cast<const float4*>(&LoS[s][jl0]);
            float4 hi0 = *reinterpret_cast<const float4*>(&HiS[s][jh0]);
            float4 hi1 = *reinterpret_cast<const float4*>(&HiS[s][jh0 + 4]);
            float hv[8] = {hi0.x, hi0.y, hi0.z, hi0.w, hi1.x, hi1.y, hi1.z, hi1.w};
#pragma unroll
            for (int a = 0; a < 8; a++) {
                acc[a].x += hv[a] * lo.x;
                acc[a].y += hv[a] * lo.y;
                acc[a].z += hv[a] * lo.z;
                acc[a].w += hv[a] * lo.w;
            }
        }
    }
    // coalesced float4 dump: warp covers one full 512B row per a
    float* bp = g_Bp + (size_t)blockIdx.x * J_;
#pragma unroll
    for (int a = 0; a < 8; a++)
        *reinterpret_cast<float4*>(&bp[(jh0 + a) * 128 + jl0]) = acc[a];
}

// ---------------------------------------------------------------------------
// Kernel 5: reduce partials over blocks -> avg_prob -> entropy terms.
// grid = 64 blocks x 256 threads (one code slot each)
// ---------------------------------------------------------------------------
__global__ void __launch_bounds__(256) k_cred() {
    int e = blockIdx.x * 256 + threadIdx.x;
    float sum = 0.f;
#pragma unroll 8
    for (int blk = 0; blk < BBLK; blk++) sum += g_Bp[blk * J_ + e];
    float avg  = sum * (1.f / 8192.f);
    float entc = -avg * __logf(fmaxf(avg, 1e-20f));

    __shared__ float sr[256];
    sr[threadIdx.x] = entc;
    __syncthreads();
    for (int s = 128; s > 0; s >>= 1) {
        if (threadIdx.x < s) sr[threadIdx.x] += sr[threadIdx.x + s];
        __syncthreads();
    }
    if (threadIdx.x == 0) g_Cp[blockIdx.x] = sr[0];
}

// ---------------------------------------------------------------------------
// Kernel 6: final combine -> aux_loss
// ---------------------------------------------------------------------------
__global__ void k_final(float* __restrict__ dout) {
    int t = threadIdx.x;   // 32 threads
    float cb = g_Cp[t] + g_Cp[t + 32];
    float cm = g_Ap[2 * t];
    float en = g_Ap[2 * t + 1];
#pragma unroll
    for (int o = 16; o > 0; o >>= 1) {
        cb += __shfl_down_sync(0xffffffffu, cb, o);
        cm += __shfl_down_sync(0xffffffffu, cm, o);
        en += __shfl_down_sync(0xffffffffu, en, o);
    }
    if (t == 0) {
        float ps_mean     = en / 8192.f;
        float commit_mean = cm / (8192.f * 14.f);
        // aux = 0.1*(per_sample_entropy - 1.0*codebook_entropy) + 1.0*commit
        dout[OUT_LOSS] = 0.1f * (ps_mean - cb) + commit_mean;
    }
}

// ---------------------------------------------------------------------------
extern "C" void kernel_launch(void* const* d_in, const int* in_sizes, int n_in,
                              void* d_out, int out_size) {
    const float* x    = (const float*)d_in[0];
    const float* Win  = (const float*)d_in[1];
    const float* bin  = (const float*)d_in[2];
    const float* Wout = (const float*)d_in[3];
    const float* bout = (const float*)d_in[4];
    float* out = (float*)d_out;

    k_inproj<<<128, 256>>>(x, Win);
    k_mid<<<32, 256>>>(bin, out);
    k_outproj<<<128, 256>>>(Wout, bout, out);
    k_avg<<<BBLK, 512>>>();
    k_cred<<<64, 256>>>();
    k_final<<<1, 32>>>(out);
}